// round 9
// baseline (speedup 1.0000x reference)
#include <cuda_runtime.h>
#include <cuda_fp16.h>
#include <cstdint>

// EdgePredictor, fp16 mma.sync.m16n8k16 + ldmatrix, 16 independent single-warp
// pipelines per CTA (512 thr). R7: warp tile = 32 edges (M=32) to halve the
// per-edge W1 ldsm traffic (smem crossbar was the R6 binder at L1=83.5%).
// Warp w owns A rows [32w,32w+32); no block barriers in the loop, only __syncwarp.

#define THREADS 512
#define A_ROW  272u   // bytes per A row (136 halves: 128 + pad)
#define W1_ROW 528u   // bytes per W1t row (264 halves)
#define W2_ROW 272u

#define OFF_W1T  0u        // [128 n][264 h] : 67584 B
#define OFF_A    67584u    // 16 warps x 32 rows x 272 B : 139264 B
#define OFF_W2T  206848u   // [32 n][136 h] : 8704 B
#define OFF_B1   215552u   // 128 f32
#define OFF_R256 216064u   // 128 f32
#define OFF_B2   216576u   // 32 f32
#define OFF_W3   216704u   // 32 f32
#define SMEM_BYTES 216832

__device__ __forceinline__ uint32_t smem_u32(const void* p) {
    uint32_t a;
    asm("{ .reg .u64 t; cvta.to.shared.u64 t, %1; cvt.u32.u64 %0, t; }" : "=r"(a) : "l"(p));
    return a;
}
__device__ __forceinline__ void ldsm4(uint32_t* r, uint32_t a) {
    asm volatile("ldmatrix.sync.aligned.m8n8.x4.shared.b16 {%0,%1,%2,%3}, [%4];"
                 : "=r"(r[0]), "=r"(r[1]), "=r"(r[2]), "=r"(r[3]) : "r"(a));
}
__device__ __forceinline__ void mma16(float* c, const uint32_t* a, uint32_t b0, uint32_t b1) {
    asm volatile("mma.sync.aligned.m16n8k16.row.col.f32.f16.f16.f32 "
                 "{%0,%1,%2,%3}, {%4,%5,%6,%7}, {%8,%9}, {%0,%1,%2,%3};"
                 : "+f"(c[0]), "+f"(c[1]), "+f"(c[2]), "+f"(c[3])
                 : "r"(a[0]), "r"(a[1]), "r"(a[2]), "r"(a[3]), "r"(b0), "r"(b1));
}
__device__ __forceinline__ uint32_t pack_h2(float a, float b) {
    __half2 h = __floats2half2_rn(a, b);
    return *(const uint32_t*)&h;
}

__global__ __launch_bounds__(THREADS, 1)
void edge_mlp_fp16(const float* __restrict__ x,
                   const int* __restrict__ ei,
                   const float* __restrict__ ea,
                   const float* __restrict__ W1g, const float* __restrict__ b1g,
                   const float* __restrict__ W2g, const float* __restrict__ b2g,
                   const float* __restrict__ W3g, const float* __restrict__ b3g,
                   float* __restrict__ out, int nE)
{
    extern __shared__ char smem[];
    const uint32_t sb = smem_u32(smem);
    const int tx = threadIdx.x;
    const int w  = tx >> 5;
    const int l  = tx & 31;

    float* b1s   = (float*)(smem + OFF_B1);
    float* r256s = (float*)(smem + OFF_R256);
    float* b2s   = (float*)(smem + OFF_B2);
    float* W3s   = (float*)(smem + OFF_W3);

    // ---- one-time weight staging (fp16, transposed) ----
    for (int idx = tx; idx < 257 * 128; idx += THREADS) {
        int k = idx >> 7, n = idx & 127;
        float v = W1g[idx];
        if (k < 256) *(__half*)(smem + OFF_W1T + n * W1_ROW + k * 2) = __float2half_rn(v);
        else         r256s[n] = v;
    }
    for (int idx = tx; idx < 128 * 32; idx += THREADS) {
        int k = idx >> 5, n = idx & 31;
        *(__half*)(smem + OFF_W2T + n * W2_ROW + k * 2) = __float2half_rn(W2g[idx]);
    }
    if (tx < 128) b1s[tx] = b1g[tx];
    if (tx < 32)  { b2s[tx] = b2g[tx]; W3s[tx] = W3g[tx]; }
    const float b3v = b3g[0];
    __syncthreads();

    // ---- per-lane fragment bases ----
    const int g  = l >> 2, t4 = l & 3;
    const int aSel  = l & 15;
    const int aColB = (l >> 4) * 16;
    const int bR = (l & 7) + ((l >> 4) & 1) * 8;
    const int bC = ((l >> 3) & 1) * 16;

    const uint32_t aWarpOff = OFF_A + (uint32_t)w * 32 * A_ROW;     // warp's 32-row strip
    const uint32_t aBase0 = sb + aWarpOff + (uint32_t)aSel * A_ROW + aColB;
    const uint32_t aBase1 = aBase0 + 16 * A_ROW;
    const uint32_t bBase1 = sb + OFF_W1T + (uint32_t)bR * W1_ROW + bC;
    const uint32_t bBase2 = sb + OFF_W2T + (uint32_t)bR * W2_ROW + bC;

    const float4* x4 = (const float4*)x;
    const int nT = (nE + 31) >> 5;
    const int stride = gridDim.x * 16;

    for (int t = blockIdx.x * 16 + w; t < nT; t += stride) {
        const int base = t << 5;

        // ---- per-tile indices in registers (one edge per lane) ----
        int srcR = 0, dstR = 0; float attrR = 0.f;
        {
            int e = base + l;
            if (e < nE) { srcR = ei[e]; dstR = ei[nE + e]; attrR = ea[e]; }
        }

        // ---- gather src feats -> A strip (fp16, 32 rows) ----
        #pragma unroll
        for (int r = 0; r < 32; r++) {
            int node = __shfl_sync(0xffffffffu, srcR, r);
            float4 ft = x4[node * 32 + l];
            uint2 u = make_uint2(pack_h2(ft.x, ft.y), pack_h2(ft.z, ft.w));
            *(uint2*)(smem + aWarpOff + (uint32_t)r * A_ROW + l * 8) = u;
        }
        __syncwarp();

        float acc[2][16][4];
        #pragma unroll
        for (int mi = 0; mi < 2; mi++)
            #pragma unroll
            for (int ni = 0; ni < 16; ni++)
                #pragma unroll
                for (int c = 0; c < 4; c++) acc[mi][ni][c] = 0.f;

        // ---- layer-1 half 0: src feats vs W1 k[0..128) ----
        #pragma unroll
        for (int ks = 0; ks < 8; ks++) {
            uint32_t a0[4], a1[4];
            ldsm4(a0, aBase0 + ks * 32);
            ldsm4(a1, aBase1 + ks * 32);
            #pragma unroll
            for (int nip = 0; nip < 8; nip++) {
                uint32_t b[4];
                ldsm4(b, bBase1 + nip * (16 * W1_ROW) + ks * 32);
                mma16(acc[0][2 * nip],     a0, b[0], b[1]);
                mma16(acc[0][2 * nip + 1], a0, b[2], b[3]);
                mma16(acc[1][2 * nip],     a1, b[0], b[1]);
                mma16(acc[1][2 * nip + 1], a1, b[2], b[3]);
            }
        }
        __syncwarp();   // LDSM reads of src done before overwrite

        // ---- gather dst feats -> A strip ----
        #pragma unroll
        for (int r = 0; r < 32; r++) {
            int node = __shfl_sync(0xffffffffu, dstR, r);
            float4 ft = x4[node * 32 + l];
            uint2 u = make_uint2(pack_h2(ft.x, ft.y), pack_h2(ft.z, ft.w));
            *(uint2*)(smem + aWarpOff + (uint32_t)r * A_ROW + l * 8) = u;
        }
        __syncwarp();

        // ---- layer-1 half 1: dst feats vs W1 k[128..256) ----
        #pragma unroll
        for (int ks = 0; ks < 8; ks++) {
            uint32_t a0[4], a1[4];
            ldsm4(a0, aBase0 + ks * 32);
            ldsm4(a1, aBase1 + ks * 32);
            #pragma unroll
            for (int nip = 0; nip < 8; nip++) {
                uint32_t b[4];
                ldsm4(b, bBase1 + nip * (16 * W1_ROW) + 256 + ks * 32);
                mma16(acc[0][2 * nip],     a0, b[0], b[1]);
                mma16(acc[0][2 * nip + 1], a0, b[2], b[3]);
                mma16(acc[1][2 * nip],     a1, b[0], b[1]);
                mma16(acc[1][2 * nip + 1], a1, b[2], b[3]);
            }
        }
        __syncwarp();   // LDSM reads done before h1 overwrite

        // ---- epilogue 1: h1 = relu(D1 + attr*r256 + b1) -> A strip (fp16) ----
        #pragma unroll
        for (int mi = 0; mi < 2; mi++) {
            const float am0 = __shfl_sync(0xffffffffu, attrR, mi * 16 + g);
            const float am1 = __shfl_sync(0xffffffffu, attrR, mi * 16 + g + 8);
            const uint32_t row0 = aWarpOff + (uint32_t)(mi * 16 + g) * A_ROW;
            const uint32_t row1 = row0 + 8 * A_ROW;
            #pragma unroll
            for (int ni = 0; ni < 16; ni++) {
                int col = ni * 8 + 2 * t4;
                float2 bb = *(const float2*)(b1s + col);
                float2 rr = *(const float2*)(r256s + col);
                float h0 = fmaxf(acc[mi][ni][0] + am0 * rr.x + bb.x, 0.f);
                float h1 = fmaxf(acc[mi][ni][1] + am0 * rr.y + bb.y, 0.f);
                float h2 = fmaxf(acc[mi][ni][2] + am1 * rr.x + bb.x, 0.f);
                float h3 = fmaxf(acc[mi][ni][3] + am1 * rr.y + bb.y, 0.f);
                *(uint32_t*)(smem + row0 + col * 2) = pack_h2(h0, h1);
                *(uint32_t*)(smem + row1 + col * 2) = pack_h2(h2, h3);
            }
        }
        __syncwarp();

        // ---- layer 2: [32 x 128] @ [128 x 32] ----
        float acc2[2][4][4];
        #pragma unroll
        for (int mi = 0; mi < 2; mi++)
            #pragma unroll
            for (int ni = 0; ni < 4; ni++)
                #pragma unroll
                for (int c = 0; c < 4; c++) acc2[mi][ni][c] = 0.f;

        #pragma unroll
        for (int ks = 0; ks < 8; ks++) {
            uint32_t a0[4], a1[4];
            ldsm4(a0, aBase0 + ks * 32);
            ldsm4(a1, aBase1 + ks * 32);
            #pragma unroll
            for (int nip = 0; nip < 2; nip++) {
                uint32_t b[4];
                ldsm4(b, bBase2 + nip * (16 * W2_ROW) + ks * 32);
                mma16(acc2[0][2 * nip],     a0, b[0], b[1]);
                mma16(acc2[0][2 * nip + 1], a0, b[2], b[3]);
                mma16(acc2[1][2 * nip],     a1, b[0], b[1]);
                mma16(acc2[1][2 * nip + 1], a1, b[2], b[3]);
            }
        }

        // ---- layer 3: relu(h2).W3 reduce(width4) + sigmoid ----
        #pragma unroll
        for (int mi = 0; mi < 2; mi++) {
            float p0 = 0.f, p1 = 0.f;
            #pragma unroll
            for (int ni = 0; ni < 4; ni++) {
                int col = ni * 8 + 2 * t4;
                float2 bb = *(const float2*)(b2s + col);
                float2 ww = *(const float2*)(W3s + col);
                p0 += fmaxf(acc2[mi][ni][0] + bb.x, 0.f) * ww.x
                    + fmaxf(acc2[mi][ni][1] + bb.y, 0.f) * ww.y;
                p1 += fmaxf(acc2[mi][ni][2] + bb.x, 0.f) * ww.x
                    + fmaxf(acc2[mi][ni][3] + bb.y, 0.f) * ww.y;
            }
            p0 += __shfl_xor_sync(0xffffffffu, p0, 1, 4);
            p0 += __shfl_xor_sync(0xffffffffu, p0, 2, 4);
            p1 += __shfl_xor_sync(0xffffffffu, p1, 1, 4);
            p1 += __shfl_xor_sync(0xffffffffu, p1, 2, 4);
            if (t4 == 0) {
                int e0 = base + mi * 16 + g, e1 = e0 + 8;
                if (e0 < nE) out[e0] = 1.f / (1.f + __expf(-(p0 + b3v)));
                if (e1 < nE) out[e1] = 1.f / (1.f + __expf(-(p1 + b3v)));
            }
        }
        __syncwarp();   // L2 LDSM done before next tile's gather overwrite
    }
}

extern "C" void kernel_launch(void* const* d_in, const int* in_sizes, int n_in,
                              void* d_out, int out_size)
{
    const float* x  = (const float*)d_in[0];
    const int*   ei = (const int*)d_in[1];
    const float* ea = (const float*)d_in[2];
    const float* W1 = (const float*)d_in[3];
    const float* b1 = (const float*)d_in[4];
    const float* W2 = (const float*)d_in[5];
    const float* b2 = (const float*)d_in[6];
    const float* W3 = (const float*)d_in[7];
    const float* b3 = (const float*)d_in[8];
    float* out = (float*)d_out;
    const int nE = out_size;

    cudaFuncSetAttribute(edge_mlp_fp16,
                         cudaFuncAttributeMaxDynamicSharedMemorySize, SMEM_BYTES);
    edge_mlp_fp16<<<148, THREADS, SMEM_BYTES>>>(x, ei, ea, W1, b1, W2, b2, W3, b3, out, nE);
}

// round 13
// speedup vs baseline: 1.9445x; 1.9445x over previous
#include <cuda_runtime.h>
#include <cuda_fp16.h>
#include <cstdint>

// EdgePredictor, fp16 mma.sync.m16n8k16 + ldmatrix, 8 independent single-warp
// pipelines per CTA (256 thr -> 255 regs/thread, no spills at M=32).
// Warp w owns a 32-row x 256-col fp16 A strip (src feats k[0,128), dst k[128,256))
// and a private stream of 32-edge tiles; single k-loop, only __syncwarp in loop.

#define THREADS 256
#define A_ROW  528u   // bytes per A row (264 halves: 256 + pad)
#define W1_ROW 528u   // bytes per W1t row (264 halves)
#define W2_ROW 272u   // bytes per W2t row (136 halves)

#define OFF_W1T  0u        // [128 n][264 h] : 67584 B
#define OFF_A    67584u    // 8 warps x 32 rows x 528 B : 135168 B
#define OFF_W2T  202752u   // [32 n][136 h] : 8704 B
#define OFF_B1   211456u   // 128 f32
#define OFF_R256 211968u   // 128 f32
#define OFF_B2   212480u   // 32 f32
#define OFF_W3   212608u   // 32 f32
#define SMEM_BYTES 212736

__device__ __forceinline__ uint32_t smem_u32(const void* p) {
    uint32_t a;
    asm("{ .reg .u64 t; cvta.to.shared.u64 t, %1; cvt.u32.u64 %0, t; }" : "=r"(a) : "l"(p));
    return a;
}
__device__ __forceinline__ void ldsm4(uint32_t* r, uint32_t a) {
    asm volatile("ldmatrix.sync.aligned.m8n8.x4.shared.b16 {%0,%1,%2,%3}, [%4];"
                 : "=r"(r[0]), "=r"(r[1]), "=r"(r[2]), "=r"(r[3]) : "r"(a));
}
__device__ __forceinline__ void mma16(float* c, const uint32_t* a, uint32_t b0, uint32_t b1) {
    asm volatile("mma.sync.aligned.m16n8k16.row.col.f32.f16.f16.f32 "
                 "{%0,%1,%2,%3}, {%4,%5,%6,%7}, {%8,%9}, {%0,%1,%2,%3};"
                 : "+f"(c[0]), "+f"(c[1]), "+f"(c[2]), "+f"(c[3])
                 : "r"(a[0]), "r"(a[1]), "r"(a[2]), "r"(a[3]), "r"(b0), "r"(b1));
}
__device__ __forceinline__ uint32_t pack_h2(float a, float b) {
    __half2 h = __floats2half2_rn(a, b);
    return *(const uint32_t*)&h;
}

__global__ __launch_bounds__(THREADS, 1)
void edge_mlp_fp16(const float* __restrict__ x,
                   const int* __restrict__ ei,
                   const float* __restrict__ ea,
                   const float* __restrict__ W1g, const float* __restrict__ b1g,
                   const float* __restrict__ W2g, const float* __restrict__ b2g,
                   const float* __restrict__ W3g, const float* __restrict__ b3g,
                   float* __restrict__ out, int nE)
{
    extern __shared__ char smem[];
    const uint32_t sb = smem_u32(smem);
    const int tx = threadIdx.x;
    const int w  = tx >> 5;
    const int l  = tx & 31;

    float* b1s   = (float*)(smem + OFF_B1);
    float* r256s = (float*)(smem + OFF_R256);
    float* b2s   = (float*)(smem + OFF_B2);
    float* W3s   = (float*)(smem + OFF_W3);

    // ---- one-time weight staging (fp16, transposed) ----
    for (int idx = tx; idx < 257 * 128; idx += THREADS) {
        int k = idx >> 7, n = idx & 127;
        float v = W1g[idx];
        if (k < 256) *(__half*)(smem + OFF_W1T + n * W1_ROW + k * 2) = __float2half_rn(v);
        else         r256s[n] = v;
    }
    for (int idx = tx; idx < 128 * 32; idx += THREADS) {
        int k = idx >> 5, n = idx & 31;
        *(__half*)(smem + OFF_W2T + n * W2_ROW + k * 2) = __float2half_rn(W2g[idx]);
    }
    if (tx < 128) b1s[tx] = b1g[tx];
    if (tx < 32)  { b2s[tx] = b2g[tx]; W3s[tx] = W3g[tx]; }
    const float b3v = b3g[0];
    __syncthreads();

    // ---- per-lane fragment bases ----
    const int g  = l >> 2, t4 = l & 3;
    const int aSel  = l & 15;
    const int aColB = (l >> 4) * 16;
    const int bR = (l & 7) + ((l >> 4) & 1) * 8;
    const int bC = ((l >> 3) & 1) * 16;

    const uint32_t aWarpOff = OFF_A + (uint32_t)w * 32 * A_ROW;     // warp's 32-row strip
    const uint32_t aBase0 = sb + aWarpOff + (uint32_t)aSel * A_ROW + aColB;
    const uint32_t aBase1 = aBase0 + 16 * A_ROW;
    const uint32_t bBase1 = sb + OFF_W1T + (uint32_t)bR * W1_ROW + bC;
    const uint32_t bBase2 = sb + OFF_W2T + (uint32_t)bR * W2_ROW + bC;

    const float4* x4 = (const float4*)x;
    const int nT = (nE + 31) >> 5;
    const int stride = gridDim.x * 8;

    for (int t = blockIdx.x * 8 + w; t < nT; t += stride) {
        const int base = t << 5;

        // ---- per-tile indices in registers (one edge per lane) ----
        int srcR = 0, dstR = 0; float attrR = 0.f;
        {
            int e = base + l;
            if (e < nE) { srcR = ei[e]; dstR = ei[nE + e]; attrR = ea[e]; }
        }

        // ---- gather src (cols 0..127) + dst (cols 128..255) -> A strip ----
        #pragma unroll
        for (int r = 0; r < 32; r++) {
            int ns = __shfl_sync(0xffffffffu, srcR, r);
            int nd = __shfl_sync(0xffffffffu, dstR, r);
            float4 fs = x4[ns * 32 + l];
            float4 fd = x4[nd * 32 + l];
            uint2 us = make_uint2(pack_h2(fs.x, fs.y), pack_h2(fs.z, fs.w));
            uint2 ud = make_uint2(pack_h2(fd.x, fd.y), pack_h2(fd.z, fd.w));
            *(uint2*)(smem + aWarpOff + (uint32_t)r * A_ROW + l * 8) = us;
            *(uint2*)(smem + aWarpOff + (uint32_t)r * A_ROW + 256 + l * 8) = ud;
        }
        __syncwarp();

        float acc[2][16][4];
        #pragma unroll
        for (int mi = 0; mi < 2; mi++)
            #pragma unroll
            for (int ni = 0; ni < 16; ni++)
                #pragma unroll
                for (int c = 0; c < 4; c++) acc[mi][ni][c] = 0.f;

        // ---- layer 1: [32 x 256] @ [256 x 128], single k-loop ----
        #pragma unroll
        for (int ks = 0; ks < 16; ks++) {
            uint32_t a0[4], a1[4];
            ldsm4(a0, aBase0 + ks * 32);
            ldsm4(a1, aBase1 + ks * 32);
            #pragma unroll
            for (int nip = 0; nip < 8; nip++) {
                uint32_t b[4];
                ldsm4(b, bBase1 + nip * (16 * W1_ROW) + ks * 32);
                mma16(acc[0][2 * nip],     a0, b[0], b[1]);
                mma16(acc[0][2 * nip + 1], a0, b[2], b[3]);
                mma16(acc[1][2 * nip],     a1, b[0], b[1]);
                mma16(acc[1][2 * nip + 1], a1, b[2], b[3]);
            }
        }
        __syncwarp();   // all layer-1 LDSM reads done before h1 overwrite

        // ---- epilogue 1: h1 = relu(D1 + attr*r256 + b1) -> A cols 0..127 ----
        #pragma unroll
        for (int mi = 0; mi < 2; mi++) {
            const float am0 = __shfl_sync(0xffffffffu, attrR, mi * 16 + g);
            const float am1 = __shfl_sync(0xffffffffu, attrR, mi * 16 + g + 8);
            const uint32_t row0 = aWarpOff + (uint32_t)(mi * 16 + g) * A_ROW;
            const uint32_t row1 = row0 + 8 * A_ROW;
            #pragma unroll
            for (int ni = 0; ni < 16; ni++) {
                int col = ni * 8 + 2 * t4;
                float2 bb = *(const float2*)(b1s + col);
                float2 rr = *(const float2*)(r256s + col);
                float h0 = fmaxf(acc[mi][ni][0] + am0 * rr.x + bb.x, 0.f);
                float h1 = fmaxf(acc[mi][ni][1] + am0 * rr.y + bb.y, 0.f);
                float h2 = fmaxf(acc[mi][ni][2] + am1 * rr.x + bb.x, 0.f);
                float h3 = fmaxf(acc[mi][ni][3] + am1 * rr.y + bb.y, 0.f);
                *(uint32_t*)(smem + row0 + col * 2) = pack_h2(h0, h1);
                *(uint32_t*)(smem + row1 + col * 2) = pack_h2(h2, h3);
            }
        }
        __syncwarp();

        // ---- layer 2: [32 x 128] @ [128 x 32] ----
        float acc2[2][4][4];
        #pragma unroll
        for (int mi = 0; mi < 2; mi++)
            #pragma unroll
            for (int ni = 0; ni < 4; ni++)
                #pragma unroll
                for (int c = 0; c < 4; c++) acc2[mi][ni][c] = 0.f;

        #pragma unroll
        for (int ks = 0; ks < 8; ks++) {
            uint32_t a0[4], a1[4];
            ldsm4(a0, aBase0 + ks * 32);
            ldsm4(a1, aBase1 + ks * 32);
            #pragma unroll
            for (int nip = 0; nip < 2; nip++) {
                uint32_t b[4];
                ldsm4(b, bBase2 + nip * (16 * W2_ROW) + ks * 32);
                mma16(acc2[0][2 * nip],     a0, b[0], b[1]);
                mma16(acc2[0][2 * nip + 1], a0, b[2], b[3]);
                mma16(acc2[1][2 * nip],     a1, b[0], b[1]);
                mma16(acc2[1][2 * nip + 1], a1, b[2], b[3]);
            }
        }

        // ---- layer 3: relu(h2).W3 reduce(width4) + sigmoid ----
        #pragma unroll
        for (int mi = 0; mi < 2; mi++) {
            float p0 = 0.f, p1 = 0.f;
            #pragma unroll
            for (int ni = 0; ni < 4; ni++) {
                int col = ni * 8 + 2 * t4;
                float2 bb = *(const float2*)(b2s + col);
                float2 ww = *(const float2*)(W3s + col);
                p0 += fmaxf(acc2[mi][ni][0] + bb.x, 0.f) * ww.x
                    + fmaxf(acc2[mi][ni][1] + bb.y, 0.f) * ww.y;
                p1 += fmaxf(acc2[mi][ni][2] + bb.x, 0.f) * ww.x
                    + fmaxf(acc2[mi][ni][3] + bb.y, 0.f) * ww.y;
            }
            p0 += __shfl_xor_sync(0xffffffffu, p0, 1, 4);
            p0 += __shfl_xor_sync(0xffffffffu, p0, 2, 4);
            p1 += __shfl_xor_sync(0xffffffffu, p1, 1, 4);
            p1 += __shfl_xor_sync(0xffffffffu, p1, 2, 4);
            if (t4 == 0) {
                int e0 = base + mi * 16 + g, e1 = e0 + 8;
                if (e0 < nE) out[e0] = 1.f / (1.f + __expf(-(p0 + b3v)));
                if (e1 < nE) out[e1] = 1.f / (1.f + __expf(-(p1 + b3v)));
            }
        }
        __syncwarp();   // L2 LDSM done before next tile's gather overwrite
    }
}

extern "C" void kernel_launch(void* const* d_in, const int* in_sizes, int n_in,
                              void* d_out, int out_size)
{
    const float* x  = (const float*)d_in[0];
    const int*   ei = (const int*)d_in[1];
    const float* ea = (const float*)d_in[2];
    const float* W1 = (const float*)d_in[3];
    const float* b1 = (const float*)d_in[4];
    const float* W2 = (const float*)d_in[5];
    const float* b2 = (const float*)d_in[6];
    const float* W3 = (const float*)d_in[7];
    const float* b3 = (const float*)d_in[8];
    float* out = (float*)d_out;
    const int nE = out_size;

    cudaFuncSetAttribute(edge_mlp_fp16,
                         cudaFuncAttributeMaxDynamicSharedMemorySize, SMEM_BYTES);
    edge_mlp_fp16<<<148, THREADS, SMEM_BYTES>>>(x, ei, ea, W1, b1, W2, b2, W3, b3, out, nE);
}

// round 14
// speedup vs baseline: 2.1283x; 1.0945x over previous
#include <cuda_runtime.h>
#include <cuda_fp16.h>
#include <cstdint>

// EdgePredictor, fp16 mma.sync.m16n8k16 + ldmatrix.
// R9: 512 threads, 8 warp-PAIRS. Pair owns one 32-edge x 256-col fp16 A strip
// (src feats k[0,128), dst k[128,256)). Layer-1 split by N: each warp computes
// N=64 cols (acc=64 regs -> fits 128-reg cap, no spills). Layer-2 split by M
// (warp does its 16 rows x all 32 n) so layer-3 reduces in-warp.
// Sync: 4x bar.sync(pair,64) per tile. Weights staged once; 148 CTAs.

#define THREADS 512
#define A_ROW  528u   // bytes per A row (264 halves: 256 + pad)
#define W1_ROW 528u
#define W2_ROW 272u

#define OFF_W1T  0u        // [128 n][264 h] : 67584 B
#define OFF_A    67584u    // 8 pairs x 32 rows x 528 B : 135168 B
#define OFF_W2T  202752u   // [32 n][136 h] : 8704 B
#define OFF_B1   211456u   // 128 f32
#define OFF_R256 211968u   // 128 f32
#define OFF_B2   212480u   // 32 f32
#define OFF_W3   212608u   // 32 f32
#define SMEM_BYTES 212736

__device__ __forceinline__ uint32_t smem_u32(const void* p) {
    uint32_t a;
    asm("{ .reg .u64 t; cvta.to.shared.u64 t, %1; cvt.u32.u64 %0, t; }" : "=r"(a) : "l"(p));
    return a;
}
__device__ __forceinline__ void ldsm4(uint32_t* r, uint32_t a) {
    asm volatile("ldmatrix.sync.aligned.m8n8.x4.shared.b16 {%0,%1,%2,%3}, [%4];"
                 : "=r"(r[0]), "=r"(r[1]), "=r"(r[2]), "=r"(r[3]) : "r"(a));
}
__device__ __forceinline__ void mma16(float* c, const uint32_t* a, uint32_t b0, uint32_t b1) {
    asm volatile("mma.sync.aligned.m16n8k16.row.col.f32.f16.f16.f32 "
                 "{%0,%1,%2,%3}, {%4,%5,%6,%7}, {%8,%9}, {%0,%1,%2,%3};"
                 : "+f"(c[0]), "+f"(c[1]), "+f"(c[2]), "+f"(c[3])
                 : "r"(a[0]), "r"(a[1]), "r"(a[2]), "r"(a[3]), "r"(b0), "r"(b1));
}
__device__ __forceinline__ uint32_t pack_h2(float a, float b) {
    __half2 h = __floats2half2_rn(a, b);
    return *(const uint32_t*)&h;
}
__device__ __forceinline__ void barp(int id) {
    asm volatile("bar.sync %0, 64;" :: "r"(id) : "memory");
}

__global__ __launch_bounds__(THREADS, 1)
void edge_mlp_fp16(const float* __restrict__ x,
                   const int* __restrict__ ei,
                   const float* __restrict__ ea,
                   const float* __restrict__ W1g, const float* __restrict__ b1g,
                   const float* __restrict__ W2g, const float* __restrict__ b2g,
                   const float* __restrict__ W3g, const float* __restrict__ b3g,
                   float* __restrict__ out, int nE)
{
    extern __shared__ char smem[];
    const uint32_t sb = smem_u32(smem);
    const int tx = threadIdx.x;
    const int w  = tx >> 5;
    const int l  = tx & 31;
    const int pair = w >> 1;
    const int half = w & 1;
    const int barid = pair + 1;

    float* b1s   = (float*)(smem + OFF_B1);
    float* r256s = (float*)(smem + OFF_R256);
    float* b2s   = (float*)(smem + OFF_B2);
    float* W3s   = (float*)(smem + OFF_W3);

    // ---- one-time weight staging (fp16, transposed) ----
    for (int idx = tx; idx < 257 * 128; idx += THREADS) {
        int k = idx >> 7, n = idx & 127;
        float v = W1g[idx];
        if (k < 256) *(__half*)(smem + OFF_W1T + n * W1_ROW + k * 2) = __float2half_rn(v);
        else         r256s[n] = v;
    }
    for (int idx = tx; idx < 128 * 32; idx += THREADS) {
        int k = idx >> 5, n = idx & 31;
        *(__half*)(smem + OFF_W2T + n * W2_ROW + k * 2) = __float2half_rn(W2g[idx]);
    }
    if (tx < 128) b1s[tx] = b1g[tx];
    if (tx < 32)  { b2s[tx] = b2g[tx]; W3s[tx] = W3g[tx]; }
    const float b3v = b3g[0];
    __syncthreads();

    // ---- per-lane fragment bases ----
    const int g  = l >> 2, t4 = l & 3;
    const int aSel  = l & 15;
    const int aColB = (l >> 4) * 16;
    const int bR = (l & 7) + ((l >> 4) & 1) * 8;
    const int bC = ((l >> 3) & 1) * 16;

    const uint32_t aStrip = OFF_A + (uint32_t)pair * 32 * A_ROW;
    const uint32_t aBase0 = sb + aStrip + (uint32_t)aSel * A_ROW + aColB;      // rows 0-15
    const uint32_t aBase1 = aBase0 + 16 * A_ROW;                               // rows 16-31
    // layer-1 B: warp's 64-col slice = n in [64*half, 64*half+64)
    const uint32_t bBase1 = sb + OFF_W1T + (uint32_t)(half * 64 + bR) * W1_ROW + bC;
    // layer-2: warp's own 16 rows, all 32 n
    const uint32_t aBase2 = sb + aStrip + (uint32_t)(half * 16 + aSel) * A_ROW + aColB;
    const uint32_t bBase2 = sb + OFF_W2T + (uint32_t)bR * W2_ROW + bC;

    const float4* x4 = (const float4*)x;
    const int nT = (nE + 31) >> 5;
    const int stride = gridDim.x * 8;

    for (int t = blockIdx.x * 8 + pair; t < nT; t += stride) {
        const int base = t << 5;

        // ---- per-tile indices (one edge per lane; both warps load all 32) ----
        int srcR = 0, dstR = 0; float attrR = 0.f;
        {
            int e = base + l;
            if (e < nE) { srcR = ei[e]; dstR = ei[nE + e]; attrR = ea[e]; }
        }

        // ---- gather: warp fills its 16 rows (src cols 0..127, dst 128..255) ----
        #pragma unroll
        for (int r = 0; r < 16; r++) {
            int row = half * 16 + r;
            int ns = __shfl_sync(0xffffffffu, srcR, row);
            int nd = __shfl_sync(0xffffffffu, dstR, row);
            float4 fs = x4[ns * 32 + l];
            float4 fd = x4[nd * 32 + l];
            uint2 us = make_uint2(pack_h2(fs.x, fs.y), pack_h2(fs.z, fs.w));
            uint2 ud = make_uint2(pack_h2(fd.x, fd.y), pack_h2(fd.z, fd.w));
            *(uint2*)(smem + aStrip + (uint32_t)row * A_ROW + l * 8) = us;
            *(uint2*)(smem + aStrip + (uint32_t)row * A_ROW + 256 + l * 8) = ud;
        }
        barp(barid);

        // ---- layer 1: [32 x 256] @ [256 x 64(warp slice)] ----
        float acc[2][8][4];
        #pragma unroll
        for (int mi = 0; mi < 2; mi++)
            #pragma unroll
            for (int ni = 0; ni < 8; ni++)
                #pragma unroll
                for (int c = 0; c < 4; c++) acc[mi][ni][c] = 0.f;

        #pragma unroll
        for (int ks = 0; ks < 16; ks++) {
            uint32_t a0[4], a1[4];
            ldsm4(a0, aBase0 + ks * 32);
            ldsm4(a1, aBase1 + ks * 32);
            #pragma unroll
            for (int nip = 0; nip < 4; nip++) {
                uint32_t b[4];
                ldsm4(b, bBase1 + nip * (16 * W1_ROW) + ks * 32);
                mma16(acc[0][2 * nip],     a0, b[0], b[1]);
                mma16(acc[0][2 * nip + 1], a0, b[2], b[3]);
                mma16(acc[1][2 * nip],     a1, b[0], b[1]);
                mma16(acc[1][2 * nip + 1], a1, b[2], b[3]);
            }
        }
        barp(barid);   // both warps' L1 LDSM reads done before h1 overwrite

        // ---- epilogue 1: h1 = relu(D1 + attr*r256 + b1) -> A cols [64*half, +64) ----
        #pragma unroll
        for (int mi = 0; mi < 2; mi++) {
            const float am0 = __shfl_sync(0xffffffffu, attrR, mi * 16 + g);
            const float am1 = __shfl_sync(0xffffffffu, attrR, mi * 16 + g + 8);
            const uint32_t row0 = aStrip + (uint32_t)(mi * 16 + g) * A_ROW;
            const uint32_t row1 = row0 + 8 * A_ROW;
            #pragma unroll
            for (int ni = 0; ni < 8; ni++) {
                int col = half * 64 + ni * 8 + 2 * t4;
                float2 bb = *(const float2*)(b1s + col);
                float2 rr = *(const float2*)(r256s + col);
                float h0 = fmaxf(acc[mi][ni][0] + am0 * rr.x + bb.x, 0.f);
                float h1 = fmaxf(acc[mi][ni][1] + am0 * rr.y + bb.y, 0.f);
                float h2 = fmaxf(acc[mi][ni][2] + am1 * rr.x + bb.x, 0.f);
                float h3 = fmaxf(acc[mi][ni][3] + am1 * rr.y + bb.y, 0.f);
                *(uint32_t*)(smem + row0 + col * 2) = pack_h2(h0, h1);
                *(uint32_t*)(smem + row1 + col * 2) = pack_h2(h2, h3);
            }
        }
        barp(barid);   // full h1 visible to both warps

        // ---- layer 2: warp's 16 rows x 32 n ----
        float acc2[4][4];
        #pragma unroll
        for (int ni = 0; ni < 4; ni++)
            #pragma unroll
            for (int c = 0; c < 4; c++) acc2[ni][c] = 0.f;

        #pragma unroll
        for (int ks = 0; ks < 8; ks++) {
            uint32_t a0[4];
            ldsm4(a0, aBase2 + ks * 32);
            #pragma unroll
            for (int nip = 0; nip < 2; nip++) {
                uint32_t b[4];
                ldsm4(b, bBase2 + nip * (16 * W2_ROW) + ks * 32);
                mma16(acc2[2 * nip],     a0, b[0], b[1]);
                mma16(acc2[2 * nip + 1], a0, b[2], b[3]);
            }
        }

        // ---- layer 3: relu(h2).W3 reduce(width4) + sigmoid ----
        {
            float p0 = 0.f, p1 = 0.f;
            #pragma unroll
            for (int ni = 0; ni < 4; ni++) {
                int col = ni * 8 + 2 * t4;
                float2 bb = *(const float2*)(b2s + col);
                float2 ww = *(const float2*)(W3s + col);
                p0 += fmaxf(acc2[ni][0] + bb.x, 0.f) * ww.x
                    + fmaxf(acc2[ni][1] + bb.y, 0.f) * ww.y;
                p1 += fmaxf(acc2[ni][2] + bb.x, 0.f) * ww.x
                    + fmaxf(acc2[ni][3] + bb.y, 0.f) * ww.y;
            }
            p0 += __shfl_xor_sync(0xffffffffu, p0, 1, 4);
            p0 += __shfl_xor_sync(0xffffffffu, p0, 2, 4);
            p1 += __shfl_xor_sync(0xffffffffu, p1, 1, 4);
            p1 += __shfl_xor_sync(0xffffffffu, p1, 2, 4);
            if (t4 == 0) {
                int e0 = base + half * 16 + g, e1 = e0 + 8;
                if (e0 < nE) out[e0] = 1.f / (1.f + __expf(-(p0 + b3v)));
                if (e1 < nE) out[e1] = 1.f / (1.f + __expf(-(p1 + b3v)));
            }
        }
        barp(barid);   // L2 LDSM done before next tile's gather overwrite
    }
}

extern "C" void kernel_launch(void* const* d_in, const int* in_sizes, int n_in,
                              void* d_out, int out_size)
{
    const float* x  = (const float*)d_in[0];
    const int*   ei = (const int*)d_in[1];
    const float* ea = (const float*)d_in[2];
    const float* W1 = (const float*)d_in[3];
    const float* b1 = (const float*)d_in[4];
    const float* W2 = (const float*)d_in[5];
    const float* b2 = (const float*)d_in[6];
    const float* W3 = (const float*)d_in[7];
    const float* b3 = (const float*)d_in[8];
    float* out = (float*)d_out;
    const int nE = out_size;

    cudaFuncSetAttribute(edge_mlp_fp16,
                         cudaFuncAttributeMaxDynamicSharedMemorySize, SMEM_BYTES);
    edge_mlp_fp16<<<148, THREADS, SMEM_BYTES>>>(x, ei, ea, W1, b1, W2, b2, W3, b3, out, nE);
}